// round 14
// baseline (speedup 1.0000x reference)
#include <cuda_runtime.h>
#include <cuda_bf16.h>
#include <math.h>

// -------- scratch (static device globals; no allocation anywhere) ----------
#define CAND_CAP   (1 << 20)
#define SMEM_KEYS  2048
#define NSAMP      256
#define NBLOCKS    592                 // 148 SMs x 4 blocks -> exactly 1 wave
#define NTHREADS   256
#define TILE_PTS   512                 // points per tile
#define TILE_F4    768                 // 512 pts * 6 floats / 4 = 768 float4
#define TILE_BYTES 12288               // 12 KB per buffer
__device__ float2 g_cand[CAND_CAP];    // .x = d2, .y = __int_as_float(index)
__device__ int    g_count;             // reset at end of each run
__device__ int    g_pub;
__device__ int    g_done;
__device__ int    g_flag;
__device__ float  g_thresh;            // d2 threshold (<= true 16th-largest d2)
__device__ float  g_bmax[NSAMP];

__device__ __forceinline__ void cp_async16(unsigned int saddr, const float4* gptr) {
    const unsigned long long ga = __cvta_generic_to_global((const void*)gptr);
    asm volatile("cp.async.ca.shared.global [%0], [%1], 16;" :: "r"(saddr), "l"(ga));
}
#define CP_COMMIT() asm volatile("cp.async.commit_group;")
#define CP_WAIT1()  asm volatile("cp.async.wait_group 1;")
#define CP_WAIT0()  asm volatile("cp.async.wait_group 0;")

// ---------------------------------------------------------------------------
// ONE persistent kernel, single wave. Coalesced cp.async smem staging fixes
// the L1tex wavefront bottleneck of per-thread AoS loads (96B-strided LDG.128
// touched ~24 lines/instr -> capped chip at ~4 TB/s).
//
// Threshold: 16th largest of nsamp maxima over DISJOINT 512-pt tiles =>
// >= 16 distinct points >= thr => thr <= global 16th-largest d^2.
// ---------------------------------------------------------------------------
__global__ void __launch_bounds__(NTHREADS, 4)
k_locse(const float* __restrict__ P,
        const float* __restrict__ W,    // (3,10) row-major
        const float* __restrict__ bb,   // (3,)
        const int*   __restrict__ ip,
        float* __restrict__ out,        // (16,6)
        int N, int nblocks, int nsamp, int ntiles)
{
    __shared__ __align__(16) unsigned char s_arena[2 * TILE_BYTES]; // 24 KB
    __shared__ float swarpf[8];
    __shared__ float sv[256];
    __shared__ float s_thr;
    __shared__ int   s_pred;
    __shared__ int   s_bits;
    __shared__ unsigned long long swarp[8];
    __shared__ unsigned long long s_win;
    __shared__ int   sel[16];

    float* buf0 = (float*)s_arena;
    float* buf1 = (float*)(s_arena + TILE_BYTES);
    unsigned long long* keys = (unsigned long long*)s_arena;  // union: used after streaming

    const int t = threadIdx.x;
    const int b = blockIdx.x;

    const int i = *ip;
    const float px = P[6 * i + 0];
    const float py = P[6 * i + 1];
    const float pz = P[6 * i + 2];

    const float4* __restrict__ Pv = (const float4*)P;
    const unsigned int sb0 = (unsigned int)__cvta_generic_to_shared(buf0);
    const unsigned int sb1 = (unsigned int)__cvta_generic_to_shared(buf1);

    // ---- prefetch this block's first tile (tile index = b) ----
    if (b < ntiles) {
        const float4* src = Pv + (long long)b * TILE_F4 + t;
        cp_async16(sb0 + t * 16u,          src);
        cp_async16(sb0 + (t + 256) * 16u,  src + 256);
        cp_async16(sb0 + (t + 512) * 16u,  src + 512);
        CP_COMMIT();
    }

    // ---- samplers: max over first tile -> g_bmax; chooser rank-selects ----
    if (b < nsamp) {
        CP_WAIT0();
        __syncthreads();
        float m = -1.0f;
        #pragma unroll
        for (int u = 0; u < 2; u++) {
            const int j = t + 256 * u;
            const float dx = buf0[6 * j + 0] - px;
            const float dy = buf0[6 * j + 1] - py;
            const float dz = buf0[6 * j + 2] - pz;
            m = fmaxf(m, dx * dx + dy * dy + dz * dz);
        }
        #pragma unroll
        for (int s = 16; s > 0; s >>= 1)
            m = fmaxf(m, __shfl_xor_sync(0xffffffffu, m, s));
        if ((t & 31) == 0) swarpf[t >> 5] = m;
        __syncthreads();
        if (t == 0) {
            float mm = swarpf[0];
            #pragma unroll
            for (int w = 1; w < 8; w++) mm = fmaxf(mm, swarpf[w]);
            g_bmax[b] = mm;
            __threadfence();
            s_pred = (atomicAdd(&g_pub, 1) == nsamp - 1);
            s_bits = 0;
        }
        __syncthreads();
        if (s_pred) {
            sv[t] = (t < nsamp) ? g_bmax[t] : -1.0f;
            __syncthreads();
            const float my = sv[t];
            int g = 0;
            #pragma unroll 16
            for (int q = 0; q < 256; q++) g += (sv[q] > my) ? 1 : 0;
            if (g >= 15 && my >= 0.0f) atomicMax(&s_bits, __float_as_int(my));
            __syncthreads();
            if (t == 0) {
                g_thresh = __int_as_float(s_bits);
                __threadfence();
                atomicExch(&g_flag, 1);
            }
        }
    }
    if (ntiles == 0 && b == 0 && t == 0) {        // degenerate small-N guard
        g_thresh = 0.0f; __threadfence(); atomicExch(&g_flag, 1);
    }

    // ---- wait for threshold (first-tile loads already in flight) ----
    if (t == 0) {
        while (atomicAdd(&g_flag, 0) == 0) __nanosleep(64);
        __threadfence();
        s_thr = g_thresh;
    }
    __syncthreads();
    const float thr = s_thr;

    // ---- main double-buffered streaming loop over this block's tiles ----
    int k = 0;
    for (int tile = b; tile < ntiles; tile += nblocks, k++) {
        const int nxt = tile + nblocks;
        if (nxt < ntiles) {
            const unsigned int snxt = (k & 1) ? sb0 : sb1;
            const float4* src = Pv + (long long)nxt * TILE_F4 + t;
            cp_async16(snxt + t * 16u,         src);
            cp_async16(snxt + (t + 256) * 16u, src + 256);
            cp_async16(snxt + (t + 512) * 16u, src + 512);
            CP_COMMIT();
            CP_WAIT1();                 // current tile's group drained
        } else {
            CP_WAIT0();
        }
        __syncthreads();
        const float* buf = (k & 1) ? buf1 : buf0;
        #pragma unroll
        for (int u = 0; u < 2; u++) {
            const int j = t + 256 * u;
            const float dx = buf[6 * j + 0] - px;
            const float dy = buf[6 * j + 1] - py;
            const float dz = buf[6 * j + 2] - pz;
            const float d2 = dx * dx + dy * dy + dz * dz;
            if (d2 >= thr) {
                const int pos = atomicAdd(&g_count, 1);
                if (pos < CAND_CAP)
                    g_cand[pos] = make_float2(d2, __int_as_float(tile * TILE_PTS + j));
            }
        }
        __syncthreads();                // protect buffer before re-issue
    }

    // ---- scalar tail (points beyond full tiles), block 0 only ----
    if (b == 0) {
        for (int j = ntiles * TILE_PTS + t; j < N; j += NTHREADS) {
            const float dx = P[6 * j + 0] - px;
            const float dy = P[6 * j + 1] - py;
            const float dz = P[6 * j + 2] - pz;
            const float d2 = dx * dx + dy * dy + dz * dz;
            if (d2 >= thr) {
                const int pos = atomicAdd(&g_count, 1);
                if (pos < CAND_CAP) g_cand[pos] = make_float2(d2, __int_as_float(j));
            }
        }
    }

    // ---- last block: exact top-16 + epilogue ----
    __threadfence();
    __syncthreads();
    if (t == 0) s_pred = (atomicAdd(&g_done, 1) == nblocks - 1);
    __syncthreads();
    if (!s_pred) return;

    __threadfence();
    int cnt = g_count;
    if (cnt > SMEM_KEYS) cnt = SMEM_KEYS;   // survivors ~1000; 2x margin

    // packed key: (bits(sqrt(d2)) << 32) | ~idx -> max == (d desc, idx asc),
    // matching jax.lax.top_k tie semantics.
    for (int q = t; q < cnt; q += NTHREADS) {
        const float2 cv = g_cand[q];
        const unsigned int db = __float_as_uint(sqrtf(cv.x));
        const unsigned int ik = ~(unsigned int)__float_as_int(cv.y);
        keys[q] = ((unsigned long long)db << 32) | ik;
    }
    __syncthreads();

    for (int r = 0; r < 16; r++) {
        unsigned long long mk = 0; int mpos = -1;
        for (int q = t; q < cnt; q += NTHREADS) {
            const unsigned long long kk = keys[q];
            if (kk > mk) { mk = kk; mpos = q; }
        }
        unsigned long long wk = mk;
        #pragma unroll
        for (int s = 16; s > 0; s >>= 1) {
            const unsigned long long o = __shfl_xor_sync(0xffffffffu, wk, s);
            if (o > wk) wk = o;
        }
        if ((t & 31) == 0) swarp[t >> 5] = wk;
        __syncthreads();
        if (t < 8) {
            unsigned long long v = swarp[t];
            #pragma unroll
            for (int s = 4; s > 0; s >>= 1) {
                const unsigned long long o = __shfl_xor_sync(0xffu, v, s);
                if (o > v) v = o;
            }
            if (t == 0) s_win = v;
        }
        __syncthreads();
        const unsigned long long win = s_win;
        if (mk == win && mpos >= 0) keys[mpos] = 0ULL;
        if (t == 0) sel[r] = (int)(~(unsigned int)(win & 0xFFFFFFFFULL));
        __syncthreads();
    }

    if (t < 16) {
        const int idx = sel[t];
        const float nx = P[6 * idx + 0];
        const float ny = P[6 * idx + 1];
        const float nz = P[6 * idx + 2];
        const float dx = px - nx, dy = py - ny, dz = pz - nz;
        const float dist = sqrtf(dx * dx + dy * dy + dz * dz);

        float feat[10] = {px, py, pz, nx, ny, nz, dx, dy, dz, dist};

        out[6 * t + 0] = nx;
        out[6 * t + 1] = ny;
        out[6 * t + 2] = nz;
        #pragma unroll
        for (int c = 0; c < 3; c++) {
            float acc = bb[c];
            #pragma unroll
            for (int j = 0; j < 10; j++)
                acc += feat[j] * W[c * 10 + j];
            out[6 * t + 3 + c] = acc;
        }
    }

    if (t == 0) {                       // reset for next graph replay
        g_count = 0;
        g_pub = 0;
        g_done = 0;
        atomicExch(&g_flag, 0);
    }
}

// ---------------------------------------------------------------------------
extern "C" void kernel_launch(void* const* d_in, const int* in_sizes, int n_in,
                              void* d_out, int out_size)
{
    const float* P  = (const float*)d_in[0];
    const float* W  = (const float*)d_in[1];
    const float* b  = (const float*)d_in[2];
    const int*   ip = (const int*)d_in[3];
    float* out = (float*)d_out;

    const int N = in_sizes[0] / 6;
    const int ntiles = N / TILE_PTS;

    int nblocks = NBLOCKS;
    if (nblocks > ntiles) nblocks = (ntiles > 0) ? ntiles : 1;

    int nsamp = NSAMP;
    if (nsamp > ntiles) nsamp = ntiles;          // may be 0 for tiny N (guarded)

    k_locse<<<nblocks, NTHREADS>>>(P, W, b, ip, out, N, nblocks, nsamp, ntiles);
}